// round 11
// baseline (speedup 1.0000x reference)
#include <cuda_runtime.h>
#include <cuda_bf16.h>
#include <math.h>

#define B_ 64
#define L_ 128
#define E_ 512
#define N_ 512
#define H_ 1024
#define G3 3072
#define KA 1536
#define NBLK 148
#define NTHR 512

#define S1 8      /* splits for gx-h / gh (Kc=128) */
#define SQ 8      /* q splits (Kc=128) */
#define SF 8      /* final rnn splits (Kc=128) */

// ---------------- device scratch (static, no allocations) ----------------
__device__ __nv_bfloat16 g_keysb[(size_t)B_ * N_ * H_];  // 67 MB
__device__ __nv_bfloat16 g_vw[(size_t)B_ * N_ * H_];     // 67 MB: value @ Wm_ctx^T
__device__ float g_gxe[(size_t)B_ * L_ * G3];            // 100 MB
__device__ float g_h[B_ * H_];
__device__ float g_xf[B_ * H_];                          // rnn_out
__device__ float g_score[B_ * N_];
__device__ float g_attn[B_ * N_];
__device__ float g_gxp[(size_t)S1 * B_ * G3];
__device__ float g_ghp[(size_t)S1 * B_ * G3];
__device__ float g_qp[(size_t)SQ * B_ * H_];
__device__ float g_fp[(size_t)SF * B_ * H_];
__device__ unsigned g_cnt2[37 * 64];   // barrier group counters (monotone)
__device__ unsigned g_cntr;            // barrier root counter (monotone)
__device__ unsigned g_gen;             // barrier generation (monotone)
__device__ unsigned g_q[4];            // work queues (reset by barrier winner)
__device__ unsigned g_bc[B_];          // per-b score-quarter counters (monotone, mod 4)

__device__ __forceinline__ float tanh_fast(float x) {
    float y;
    asm("tanh.approx.f32 %0, %1;" : "=f"(y) : "f"(x));
    return y;
}

// ---------------- 2-level grid barrier (PROVEN in round 8) ----------------
__device__ __forceinline__ void gbar(unsigned& target, int resetq) {
    __syncthreads();
    if (threadIdx.x == 0) {
        __threadfence();
        unsigned v = atomicAdd(&g_cnt2[(blockIdx.x >> 2) * 64], 1u);
        if ((v & 3u) == 3u) {                       // last of 4 in group
            unsigned r = atomicAdd(&g_cntr, 1u);
            if (r % 37u == 36u) {                   // last group
                if (resetq >= 0) atomicExch(&g_q[resetq], 0u);
                __threadfence();
                atomicAdd(&g_gen, 1u);
            }
        }
        while ((int)(*(volatile unsigned*)&g_gen - target) < 0) { }
        target++;
    }
    __syncthreads();
}

__device__ __forceinline__ int qfetch(int c, int* s_u) {
    __syncthreads();
    if (threadIdx.x == 0) *s_u = (int)atomicAdd(&g_q[c], 1u);
    __syncthreads();
    return *s_u;
}

// ---------------- bf16 split helpers ----------------
__device__ __forceinline__ void split2(float2 v, unsigned& hi, unsigned& lo) {
    __nv_bfloat16 hx = __float2bfloat16_rn(v.x);
    __nv_bfloat16 hy = __float2bfloat16_rn(v.y);
    float rx = v.x - __bfloat162float(hx);
    float ry = v.y - __bfloat162float(hy);
    __nv_bfloat162 h2; h2.x = hx; h2.y = hy;
    __nv_bfloat162 l2 = __floats2bfloat162_rn(rx, ry);
    hi = *(unsigned*)&h2;
    lo = *(unsigned*)&l2;
}

#define MMA16816(c0,c1,c2,c3,a0,a1,a2,a3,b0,b1) \
    asm volatile("mma.sync.aligned.m16n8k16.row.col.f32.bf16.bf16.f32 " \
        "{%0,%1,%2,%3},{%4,%5,%6,%7},{%8,%9},{%0,%1,%2,%3};" \
        : "+f"(c0),"+f"(c1),"+f"(c2),"+f"(c3) \
        : "r"(a0),"r"(a1),"r"(a2),"r"(a3),"r"(b0),"r"(b1))

// ---------------- 64(M) x 128(N) x Kc GEMM tile via split-bf16 MMA ------------
// C[m][n] = sum_k Ap[m*lda+k] * Wp[n*ldw+k]   (hh + hl + lh)
__device__ __forceinline__ void gemm_mma(
    const float* __restrict__ Ap, int lda,
    const float* __restrict__ Wp, int ldw,
    void* Co, int ldc, int Kc, int bf16out, float* smf)
{
    unsigned* smu = (unsigned*)smf;
    const int tid = threadIdx.x;
    const int lane = tid & 31;
    const int g = lane >> 2, tg = lane & 3;
    const int wm = ((tid >> 5) >> 2) << 4;
    const int wn = ((tid >> 5) & 3) << 5;
    const int nkt = Kc >> 4;
    const int arow = tid >> 3, akp = tid & 7;

    float acc[4][4] = {};

    float2 apf  = __ldcg((const float2*)(Ap + (size_t)arow * lda + 2 * akp));
    float2 wpf0 = *(const float2*)(Wp + (size_t)arow * ldw + 2 * akp);
    float2 wpf1 = *(const float2*)(Wp + (size_t)(arow + 64) * ldw + 2 * akp);

    __syncthreads();
    for (int kt = 0; kt < nkt; kt++) {
        unsigned* buf = smu + (kt & 1) * 4608;
        unsigned hi, lo;
        split2(apf, hi, lo);
        buf[arow * 12 + akp] = hi;
        buf[768 + arow * 12 + akp] = lo;
        split2(wpf0, hi, lo);
        buf[1536 + arow * 12 + akp] = hi;
        buf[3072 + arow * 12 + akp] = lo;
        split2(wpf1, hi, lo);
        buf[1536 + (arow + 64) * 12 + akp] = hi;
        buf[3072 + (arow + 64) * 12 + akp] = lo;
        if (kt + 1 < nkt) {
            const float* A2 = Ap + (kt + 1) * 16;
            const float* W2 = Wp + (kt + 1) * 16;
            apf  = __ldcg((const float2*)(A2 + (size_t)arow * lda + 2 * akp));
            wpf0 = *(const float2*)(W2 + (size_t)arow * ldw + 2 * akp);
            wpf1 = *(const float2*)(W2 + (size_t)(arow + 64) * ldw + 2 * akp);
        }
        __syncthreads();
        unsigned a0h = buf[(wm + g) * 12 + tg];
        unsigned a1h = buf[(wm + g + 8) * 12 + tg];
        unsigned a2h = buf[(wm + g) * 12 + tg + 4];
        unsigned a3h = buf[(wm + g + 8) * 12 + tg + 4];
        unsigned a0l = buf[768 + (wm + g) * 12 + tg];
        unsigned a1l = buf[768 + (wm + g + 8) * 12 + tg];
        unsigned a2l = buf[768 + (wm + g) * 12 + tg + 4];
        unsigned a3l = buf[768 + (wm + g + 8) * 12 + tg + 4];
#pragma unroll
        for (int blk = 0; blk < 4; blk++) {
            int r = (wn + blk * 8 + g) * 12;
            unsigned b0h = buf[1536 + r + tg];
            unsigned b1h = buf[1536 + r + tg + 4];
            unsigned b0l = buf[3072 + r + tg];
            unsigned b1l = buf[3072 + r + tg + 4];
            MMA16816(acc[blk][0], acc[blk][1], acc[blk][2], acc[blk][3],
                     a0h, a1h, a2h, a3h, b0h, b1h);
            MMA16816(acc[blk][0], acc[blk][1], acc[blk][2], acc[blk][3],
                     a0h, a1h, a2h, a3h, b0l, b1l);
            MMA16816(acc[blk][0], acc[blk][1], acc[blk][2], acc[blk][3],
                     a0l, a1l, a2l, a3l, b0h, b1h);
        }
    }
    if (!bf16out) {
        float* C = (float*)Co;
#pragma unroll
        for (int blk = 0; blk < 4; blk++) {
            int col = wn + blk * 8 + 2 * tg;
            *(float2*)(C + (size_t)(wm + g) * ldc + col) =
                make_float2(acc[blk][0], acc[blk][1]);
            *(float2*)(C + (size_t)(wm + g + 8) * ldc + col) =
                make_float2(acc[blk][2], acc[blk][3]);
        }
    } else {
        __nv_bfloat16* C = (__nv_bfloat16*)Co;
#pragma unroll
        for (int blk = 0; blk < 4; blk++) {
            int col = wn + blk * 8 + 2 * tg;
            *(__nv_bfloat162*)(C + (size_t)(wm + g) * ldc + col) =
                __floats2bfloat162_rn(acc[blk][0], acc[blk][1]);
            *(__nv_bfloat162*)(C + (size_t)(wm + g + 8) * ldc + col) =
                __floats2bfloat162_rn(acc[blk][2], acc[blk][3]);
        }
    }
}

// ---------------- the one persistent kernel ----------------
__global__ __launch_bounds__(NTHR, 1) void decoder_all(
    const float* __restrict__ emb,   const float* __restrict__ value,
    const float* __restrict__ vmask, const float* __restrict__ state,
    const float* __restrict__ W_ih,  const float* __restrict__ b_ih,
    const float* __restrict__ W_hh,  const float* __restrict__ b_hh,
    const float* __restrict__ Wq,    const float* __restrict__ Wk,
    const float* __restrict__ v_att, const float* __restrict__ Wm,
    const float* __restrict__ bm,
    float* __restrict__ out, float* __restrict__ attn_out)
{
    __shared__ float sm[9216];   // 36 KB
    __shared__ float red[32];
    __shared__ int   s_u;
    __shared__ int   s_flag;
    const int bid = blockIdx.x, tid = threadIdx.x;
    unsigned target = 0;
    if (tid == 0) target = *(volatile unsigned*)&g_gen + 1u;
    __syncthreads();

    // ===== phase 0: init h; keys + VW + gxe GEMMs (queue 0) =====
    {
        int i = bid * NTHR + tid;
        if (i < B_ * H_) g_h[i] = state[i];
    }
    for (;;) {
        int u = qfetch(0, &s_u);
        if (u >= 8192 + 3072) break;
        if (u < 8192) {
            int mt = u >> 4, sub = u & 15;
            if (sub < 8) {
                gemm_mma(value + (size_t)mt * 64 * H_, H_,
                         Wk + (size_t)sub * 128 * H_, H_,
                         g_keysb + (size_t)mt * 64 * H_ + sub * 128, H_, H_, 1, sm);
            } else {
                int nt = sub - 8;
                gemm_mma(value + (size_t)mt * 64 * H_, H_,
                         Wm + (size_t)nt * 128 * 2 * H_ + H_, 2 * H_,
                         g_vw + (size_t)mt * 64 * H_ + nt * 128, H_, H_, 1, sm);
            }
        } else {
            int u2 = u - 8192;
            int mt = u2 / 24, nt = u2 % 24;
            gemm_mma(emb + (size_t)mt * 64 * E_, E_,
                     W_ih + (size_t)nt * 128 * KA, KA,
                     g_gxe + (size_t)mt * 64 * G3 + nt * 128, G3, E_, 0, sm);
        }
    }
    gbar(target, 0);

    for (int t = 0; t < L_; t++) {
        // ---- P1: gx-h (192) + gh (192), Kc=128, queue 1 ----
        for (;;) {
            int u = qfetch(1, &s_u);
            if (u >= 384) break;
            if (u < 192) {
                int nt = u % 24, s = u / 24;
                gemm_mma(g_h + s * 128, H_,
                         W_ih + (size_t)nt * 128 * KA + E_ + s * 128, KA,
                         g_gxp + (size_t)s * B_ * G3 + nt * 128, G3, 128, 0, sm);
            } else {
                int u2 = u - 192;
                int nt = u2 % 24, s = u2 / 24;
                gemm_mma(g_h + s * 128, H_,
                         W_hh + (size_t)nt * 128 * H_ + s * 128, H_,
                         g_ghp + (size_t)s * B_ * G3 + nt * 128, G3, 128, 0, sm);
            }
        }
        gbar(target, 1);

        // ---- P2: GRU elementwise ----
        {
            int i = bid * NTHR + tid;
            if (i < B_ * H_) {
                int b = i >> 10, j = i & 1023;
                const float* ge = &g_gxe[(size_t)(b * L_ + t) * G3];
                float gxr = ge[j], gxz = ge[H_ + j], gxn = ge[2 * H_ + j];
                float ghr = 0.f, ghz = 0.f, ghn = 0.f;
#pragma unroll
                for (int s = 0; s < S1; s++) {
                    const float* p = &g_gxp[((size_t)s * B_ + b) * G3];
                    gxr += __ldcg(p + j); gxz += __ldcg(p + H_ + j); gxn += __ldcg(p + 2 * H_ + j);
                }
#pragma unroll
                for (int s = 0; s < S1; s++) {
                    const float* p = &g_ghp[((size_t)s * B_ + b) * G3];
                    ghr += __ldcg(p + j); ghz += __ldcg(p + H_ + j); ghn += __ldcg(p + 2 * H_ + j);
                }
                float r = 1.f / (1.f + expf(-(gxr + b_ih[j]        + ghr + b_hh[j])));
                float z = 1.f / (1.f + expf(-(gxz + b_ih[H_ + j]   + ghz + b_hh[H_ + j])));
                float n = tanhf(gxn + b_ih[2 * H_ + j] + r * (ghn + b_hh[2 * H_ + j]));
                float h = g_h[i];
                g_xf[i] = (1.f - z) * n + z * h;
            }
        }
        gbar(target, -1);

        // ---- P3: q GEMM, 64 static tiles (SQ=8, Kc=128) ----
        if (bid < 64) {
            int s = bid >> 3, nt = bid & 7;
            gemm_mma(g_xf + s * 128, H_,
                     Wq + (size_t)nt * 128 * H_ + s * 128, H_,
                     g_qp + (size_t)s * B_ * H_ + nt * 128, H_, 128, 0, sm);
        }
        gbar(target, -1);

        // ---- PA: score quarters (256) + final-rnn tiles (64), queue 2 ----
        for (;;) {
            int u = qfetch(2, &s_u);
            if (u >= 320) break;
            if (u < 256) {
                int b = u >> 2, qtr = u & 3;
                // stage reduced q + v_att
                for (int j = tid; j < H_; j += NTHR) {
                    float a = 0.f;
#pragma unroll
                    for (int s = 0; s < SQ; s++)
                        a += __ldcg(&g_qp[((size_t)s * B_ + b) * H_ + j]);
                    sm[j] = a;
                    sm[H_ + j] = v_att[j];
                }
                __syncthreads();
                int w = tid >> 5, lane = tid & 31;
                for (int i = 0; i < 8; i++) {
                    int n = qtr * 128 + w * 8 + i;
                    const uint4* kp = (const uint4*)(g_keysb + (size_t)(b * N_ + n) * H_);
                    float acc = 0.f;
#pragma unroll
                    for (int j2 = 0; j2 < 4; j2++) {
                        uint4 kv = kp[lane + 32 * j2];
                        int c8 = (lane + 32 * j2) << 3;
                        float4 q0 = *(const float4*)(sm + c8);
                        float4 q1 = *(const float4*)(sm + c8 + 4);
                        float4 v0 = *(const float4*)(sm + H_ + c8);
                        float4 v1 = *(const float4*)(sm + H_ + c8 + 4);
                        acc += v0.x * tanh_fast(q0.x + __uint_as_float(kv.x << 16));
                        acc += v0.y * tanh_fast(q0.y + __uint_as_float(kv.x & 0xFFFF0000u));
                        acc += v0.z * tanh_fast(q0.z + __uint_as_float(kv.y << 16));
                        acc += v0.w * tanh_fast(q0.w + __uint_as_float(kv.y & 0xFFFF0000u));
                        acc += v1.x * tanh_fast(q1.x + __uint_as_float(kv.z << 16));
                        acc += v1.y * tanh_fast(q1.y + __uint_as_float(kv.z & 0xFFFF0000u));
                        acc += v1.z * tanh_fast(q1.z + __uint_as_float(kv.w << 16));
                        acc += v1.w * tanh_fast(q1.w + __uint_as_float(kv.w & 0xFFFF0000u));
                    }
#pragma unroll
                    for (int o = 16; o; o >>= 1) acc += __shfl_xor_sync(0xffffffffu, acc, o);
                    if (lane == 0) {
                        float mk = vmask[b * N_ + n];
                        g_score[b * N_ + n] = (mk > 0.f) ? acc : -1e9f;
                    }
                }
                // 4th finisher of b runs the (cheap) softmax
                __syncthreads();
                if (tid == 0) {
                    __threadfence();
                    unsigned old = atomicAdd(&g_bc[b], 1u);
                    s_flag = ((old & 3u) == 3u) ? 1 : 0;
                }
                __syncthreads();
                if (s_flag) {
                    __threadfence();
                    float s0 = __ldcg(&g_score[b * N_ + tid]);
                    float m = s0;
#pragma unroll
                    for (int o = 16; o; o >>= 1) m = fmaxf(m, __shfl_xor_sync(0xffffffffu, m, o));
                    if (lane == 0) red[w] = m;
                    __syncthreads();
                    float M = red[0];
#pragma unroll
                    for (int i2 = 1; i2 < 16; i2++) M = fmaxf(M, red[i2]);
                    float p = expf(s0 - M);
                    float ss = p;
#pragma unroll
                    for (int o = 16; o; o >>= 1) ss += __shfl_xor_sync(0xffffffffu, ss, o);
                    if (lane == 0) red[16 + w] = ss;
                    __syncthreads();
                    float Z = red[16];
#pragma unroll
                    for (int i2 = 1; i2 < 16; i2++) Z += red[16 + i2];
                    float a = p / Z;
                    g_attn[b * N_ + tid] = a;
                    attn_out[((size_t)b * L_ + t) * N_ + tid] = a;
                }
            } else {
                // final-rnn tile: s 0..7, nt 0..7, Kc=128
                int u2 = u - 256;
                int s = u2 >> 3, nt = u2 & 7;
                gemm_mma(g_xf + s * 128, H_,
                         Wm + (size_t)nt * 128 * 2 * H_ + s * 128, 2 * H_,
                         g_fp + (size_t)s * B_ * H_ + nt * 128, H_, 128, 0, sm);
            }
        }
        gbar(target, 2);

        // ---- P8: fused ctx-from-VW + final sum + tanh (128 static units) ----
        if (bid < 128) {
            int b = bid >> 1, hb = bid & 1;
            sm[tid] = __ldcg(&g_attn[b * N_ + tid]);
            __syncthreads();
            int h = hb * 512 + tid;
            const __nv_bfloat16* vp = g_vw + (size_t)b * N_ * H_ + h;
            float fc = 0.f;
#pragma unroll 8
            for (int n = 0; n < N_; n++)
                fc += sm[n] * __bfloat162float(vp[(size_t)n * H_]);
            float a = bm[h] + fc;
#pragma unroll
            for (int s = 0; s < SF; s++)
                a += __ldcg(&g_fp[((size_t)s * B_ + b) * H_ + h]);
            float y = tanhf(a);
            out[((size_t)b * L_ + t) * H_ + h] = y;
            g_h[b * H_ + h] = y;
        }
        gbar(target, -1);
    }
}

// ---------------- launch: ONE graph node ----------------
extern "C" void kernel_launch(void* const* d_in, const int* in_sizes, int n_in,
                              void* d_out, int out_size) {
    const float* emb    = (const float*)d_in[0];
    const float* value  = (const float*)d_in[1];
    const float* vmask  = (const float*)d_in[2];
    const float* state  = (const float*)d_in[3];
    const float* W_ih   = (const float*)d_in[4];
    const float* b_ih   = (const float*)d_in[5];
    const float* W_hh   = (const float*)d_in[6];
    const float* b_hh   = (const float*)d_in[7];
    const float* Wq     = (const float*)d_in[8];
    const float* Wk     = (const float*)d_in[9];
    const float* v_att  = (const float*)d_in[10];
    const float* Wm     = (const float*)d_in[11];
    const float* bm     = (const float*)d_in[12];

    float* out      = (float*)d_out;                 // outputs: B x L x H
    float* attn_out = out + (size_t)B_ * L_ * H_;    // attns:   B x L x N

    decoder_all<<<NBLK, NTHR>>>(emb, value, vmask, state, W_ih, b_ih, W_hh, b_hh,
                                Wq, Wk, v_att, Wm, bm, out, attn_out);
}

// round 12
// speedup vs baseline: 1.4321x; 1.4321x over previous
#include <cuda_runtime.h>
#include <cuda_bf16.h>
#include <math.h>

#define B_ 64
#define L_ 128
#define E_ 512
#define N_ 512
#define H_ 1024
#define G3 3072
#define KA 1536
#define NBLK 148
#define NTHR 512

#define S1 8      /* splits for gx-h / gh (Kc=128) */
#define SQ 16     /* q splits (Kc=64) */
#define SF 8      /* final rnn splits (Kc=128) */

#define Q1_UNITS 384
#define Q2_UNITS 320     /* 128 q + 64 final-rnn + 128 score halves */
#define Q1_STRIDE 532u   /* 384 + 148 terminal fetches per step */
#define Q2_STRIDE 468u   /* 320 + 148 terminal fetches per step */

// ---------------- device scratch (static, no allocations) ----------------
__device__ __nv_bfloat16 g_keysb[(size_t)B_ * N_ * H_];  // 67 MB
__device__ __nv_bfloat16 g_vw[(size_t)B_ * N_ * H_];     // 67 MB: value @ Wm_ctx^T
__device__ float g_gxe[(size_t)B_ * L_ * G3];            // 100 MB
__device__ float g_h[B_ * H_];
__device__ float g_xf[B_ * H_];                          // rnn_out
__device__ float g_score[B_ * N_];
__device__ float g_fc[B_ * H_];                          // final ctx-part
__device__ float g_gxp[(size_t)S1 * B_ * G3];
__device__ float g_ghp[(size_t)S1 * B_ * G3];
__device__ float g_qp[(size_t)SQ * B_ * H_];
__device__ float g_fp[(size_t)SF * B_ * H_];
// monotone sync state (reset by last CTA at end of each launch)
__device__ unsigned g_q0, g_q1, g_q2;
__device__ unsigned c_p1, c_p2, c_q, c_fin, c_p8, c_end;
__device__ unsigned g_bc[B_];

__device__ __forceinline__ float tanh_fast(float x) {
    float y;
    asm("tanh.approx.f32 %0, %1;" : "=f"(y) : "f"(x));
    return y;
}

// spin until *c >= tgt (CTA-wide)
__device__ __forceinline__ void waitc(unsigned* c, unsigned tgt) {
    __syncthreads();
    if (threadIdx.x == 0) {
        while ((int)(*(volatile unsigned*)c - tgt) < 0) { }
    }
    __syncthreads();
}
// post completion: fence + inc (CTA-wide entry)
__device__ __forceinline__ void incc(unsigned* c) {
    __syncthreads();
    if (threadIdx.x == 0) { __threadfence(); atomicAdd(c, 1u); }
    __syncthreads();
}

// ---------------- bf16 split helpers ----------------
__device__ __forceinline__ void split2(float2 v, unsigned& hi, unsigned& lo) {
    __nv_bfloat16 hx = __float2bfloat16_rn(v.x);
    __nv_bfloat16 hy = __float2bfloat16_rn(v.y);
    float rx = v.x - __bfloat162float(hx);
    float ry = v.y - __bfloat162float(hy);
    __nv_bfloat162 h2; h2.x = hx; h2.y = hy;
    __nv_bfloat162 l2 = __floats2bfloat162_rn(rx, ry);
    hi = *(unsigned*)&h2;
    lo = *(unsigned*)&l2;
}

#define MMA16816(c0,c1,c2,c3,a0,a1,a2,a3,b0,b1) \
    asm volatile("mma.sync.aligned.m16n8k16.row.col.f32.bf16.bf16.f32 " \
        "{%0,%1,%2,%3},{%4,%5,%6,%7},{%8,%9},{%0,%1,%2,%3};" \
        : "+f"(c0),"+f"(c1),"+f"(c2),"+f"(c3) \
        : "r"(a0),"r"(a1),"r"(a2),"r"(a3),"r"(b0),"r"(b1))

// ---------------- 64(M) x 128(N) x Kc GEMM tile via split-bf16 MMA ------------
// C[m][n] = sum_k Ap[m*lda+k] * Wp[n*ldw+k]   (hh + hl + lh; A read via __ldcg)
__device__ __forceinline__ void gemm_mma(
    const float* __restrict__ Ap, int lda,
    const float* __restrict__ Wp, int ldw,
    void* Co, int ldc, int Kc, int bf16out, float* smf)
{
    unsigned* smu = (unsigned*)smf;
    const int tid = threadIdx.x;
    const int lane = tid & 31;
    const int g = lane >> 2, tg = lane & 3;
    const int wm = ((tid >> 5) >> 2) << 4;
    const int wn = ((tid >> 5) & 3) << 5;
    const int nkt = Kc >> 4;
    const int arow = tid >> 3, akp = tid & 7;

    float acc[4][4] = {};

    float2 apf  = __ldcg((const float2*)(Ap + (size_t)arow * lda + 2 * akp));
    float2 wpf0 = *(const float2*)(Wp + (size_t)arow * ldw + 2 * akp);
    float2 wpf1 = *(const float2*)(Wp + (size_t)(arow + 64) * ldw + 2 * akp);

    __syncthreads();
    for (int kt = 0; kt < nkt; kt++) {
        unsigned* buf = smu + (kt & 1) * 4608;
        unsigned hi, lo;
        split2(apf, hi, lo);
        buf[arow * 12 + akp] = hi;
        buf[768 + arow * 12 + akp] = lo;
        split2(wpf0, hi, lo);
        buf[1536 + arow * 12 + akp] = hi;
        buf[3072 + arow * 12 + akp] = lo;
        split2(wpf1, hi, lo);
        buf[1536 + (arow + 64) * 12 + akp] = hi;
        buf[3072 + (arow + 64) * 12 + akp] = lo;
        if (kt + 1 < nkt) {
            const float* A2 = Ap + (kt + 1) * 16;
            const float* W2 = Wp + (kt + 1) * 16;
            apf  = __ldcg((const float2*)(A2 + (size_t)arow * lda + 2 * akp));
            wpf0 = *(const float2*)(W2 + (size_t)arow * ldw + 2 * akp);
            wpf1 = *(const float2*)(W2 + (size_t)(arow + 64) * ldw + 2 * akp);
        }
        __syncthreads();
        unsigned a0h = buf[(wm + g) * 12 + tg];
        unsigned a1h = buf[(wm + g + 8) * 12 + tg];
        unsigned a2h = buf[(wm + g) * 12 + tg + 4];
        unsigned a3h = buf[(wm + g + 8) * 12 + tg + 4];
        unsigned a0l = buf[768 + (wm + g) * 12 + tg];
        unsigned a1l = buf[768 + (wm + g + 8) * 12 + tg];
        unsigned a2l = buf[768 + (wm + g) * 12 + tg + 4];
        unsigned a3l = buf[768 + (wm + g + 8) * 12 + tg + 4];
#pragma unroll
        for (int blk = 0; blk < 4; blk++) {
            int r = (wn + blk * 8 + g) * 12;
            unsigned b0h = buf[1536 + r + tg];
            unsigned b1h = buf[1536 + r + tg + 4];
            unsigned b0l = buf[3072 + r + tg];
            unsigned b1l = buf[3072 + r + tg + 4];
            MMA16816(acc[blk][0], acc[blk][1], acc[blk][2], acc[blk][3],
                     a0h, a1h, a2h, a3h, b0h, b1h);
            MMA16816(acc[blk][0], acc[blk][1], acc[blk][2], acc[blk][3],
                     a0h, a1h, a2h, a3h, b0l, b1l);
            MMA16816(acc[blk][0], acc[blk][1], acc[blk][2], acc[blk][3],
                     a0l, a1l, a2l, a3l, b0h, b1h);
        }
    }
    if (!bf16out) {
        float* C = (float*)Co;
#pragma unroll
        for (int blk = 0; blk < 4; blk++) {
            int col = wn + blk * 8 + 2 * tg;
            *(float2*)(C + (size_t)(wm + g) * ldc + col) =
                make_float2(acc[blk][0], acc[blk][1]);
            *(float2*)(C + (size_t)(wm + g + 8) * ldc + col) =
                make_float2(acc[blk][2], acc[blk][3]);
        }
    } else {
        __nv_bfloat16* C = (__nv_bfloat16*)Co;
#pragma unroll
        for (int blk = 0; blk < 4; blk++) {
            int col = wn + blk * 8 + 2 * tg;
            *(__nv_bfloat162*)(C + (size_t)(wm + g) * ldc + col) =
                __floats2bfloat162_rn(acc[blk][0], acc[blk][1]);
            *(__nv_bfloat162*)(C + (size_t)(wm + g + 8) * ldc + col) =
                __floats2bfloat162_rn(acc[blk][2], acc[blk][3]);
        }
    }
}

// ---------------- the one persistent kernel ----------------
__global__ __launch_bounds__(NTHR, 1) void decoder_all(
    const float* __restrict__ emb,   const float* __restrict__ value,
    const float* __restrict__ vmask, const float* __restrict__ state,
    const float* __restrict__ W_ih,  const float* __restrict__ b_ih,
    const float* __restrict__ W_hh,  const float* __restrict__ b_hh,
    const float* __restrict__ Wq,    const float* __restrict__ Wk,
    const float* __restrict__ v_att, const float* __restrict__ Wm,
    const float* __restrict__ bm,
    float* __restrict__ out, float* __restrict__ attn_out)
{
    __shared__ float sm[9216];   // 36 KB
    __shared__ float red[32];
    __shared__ int   s_u;
    __shared__ int   s_flag;
    const int bid = blockIdx.x, tid = threadIdx.x;

    // ===== phase 0: init h; keys + VW + gxe GEMMs (queue 0) =====
    {
        int i = bid * NTHR + tid;
        if (i < B_ * H_) g_h[i] = state[i];
    }
    for (;;) {
        __syncthreads();
        if (tid == 0) s_u = (int)atomicAdd(&g_q0, 1u);
        __syncthreads();
        int u = s_u;
        if (u >= 8192 + 3072) break;
        if (u < 8192) {
            int mt = u >> 4, sub = u & 15;
            if (sub < 8) {
                gemm_mma(value + (size_t)mt * 64 * H_, H_,
                         Wk + (size_t)sub * 128 * H_, H_,
                         g_keysb + (size_t)mt * 64 * H_ + sub * 128, H_, H_, 1, sm);
            } else {
                int nt = sub - 8;
                gemm_mma(value + (size_t)mt * 64 * H_, H_,
                         Wm + (size_t)nt * 128 * 2 * H_ + H_, 2 * H_,
                         g_vw + (size_t)mt * 64 * H_ + nt * 128, H_, H_, 1, sm);
            }
        } else {
            int u2 = u - 8192;
            int mt = u2 / 24, nt = u2 % 24;
            gemm_mma(emb + (size_t)mt * 64 * E_, E_,
                     W_ih + (size_t)nt * 128 * KA, KA,
                     g_gxe + (size_t)mt * 64 * G3 + nt * 128, G3, E_, 0, sm);
        }
    }
    incc(&c_p8);   // phase-0 complete marker (c_p8 reaches 148)

    for (int t = 0; t < L_; t++) {
        const unsigned t1 = (unsigned)(t + 1);
        waitc(&c_p8, 148u * t1);   // h(t) ready (and phase 0 for t=0)

        // ---- P1: gx-h (192) + gh (192), Kc=128, queue 1 (stride 532/step) ----
        {
            int prev = 0;
            for (;;) {
                __syncthreads();
                if (tid == 0) {
                    if (prev) { __threadfence(); atomicAdd(&c_p1, 1u); }
                    s_u = (int)(atomicAdd(&g_q1, 1u) - Q1_STRIDE * (unsigned)t);
                }
                __syncthreads();
                int u = s_u;
                if (u >= Q1_UNITS) break;
                if (u < 192) {
                    int nt = u % 24, s = u / 24;
                    gemm_mma(g_h + s * 128, H_,
                             W_ih + (size_t)nt * 128 * KA + E_ + s * 128, KA,
                             g_gxp + (size_t)s * B_ * G3 + nt * 128, G3, 128, 0, sm);
                } else {
                    int u2 = u - 192;
                    int nt = u2 % 24, s = u2 / 24;
                    gemm_mma(g_h + s * 128, H_,
                             W_hh + (size_t)nt * 128 * H_ + s * 128, H_,
                             g_ghp + (size_t)s * B_ * G3 + nt * 128, G3, 128, 0, sm);
                }
                prev = 1;
            }
        }
        waitc(&c_p1, 384u * t1);

        // ---- P2: GRU elementwise ----
        {
            int i = bid * NTHR + tid;
            if (i < B_ * H_) {
                int b = i >> 10, j = i & 1023;
                const float* ge = &g_gxe[(size_t)(b * L_ + t) * G3];
                float gxr = ge[j], gxz = ge[H_ + j], gxn = ge[2 * H_ + j];
                float ghr = 0.f, ghz = 0.f, ghn = 0.f;
#pragma unroll
                for (int s = 0; s < S1; s++) {
                    const float* p = &g_gxp[((size_t)s * B_ + b) * G3];
                    gxr += __ldcg(p + j); gxz += __ldcg(p + H_ + j); gxn += __ldcg(p + 2 * H_ + j);
                }
#pragma unroll
                for (int s = 0; s < S1; s++) {
                    const float* p = &g_ghp[((size_t)s * B_ + b) * G3];
                    ghr += __ldcg(p + j); ghz += __ldcg(p + H_ + j); ghn += __ldcg(p + 2 * H_ + j);
                }
                float r = 1.f / (1.f + expf(-(gxr + b_ih[j]        + ghr + b_hh[j])));
                float z = 1.f / (1.f + expf(-(gxz + b_ih[H_ + j]   + ghz + b_hh[H_ + j])));
                float n = tanhf(gxn + b_ih[2 * H_ + j] + r * (ghn + b_hh[2 * H_ + j]));
                float h = g_h[i];
                g_xf[i] = (1.f - z) * n + z * h;
            }
        }
        incc(&c_p2);
        waitc(&c_p2, 148u * t1);

        // ---- Q2: q tiles (128) | final-rnn (64) | score halves (128); stride 468/step
        {
            int prevc = 0;   // 0 none, 1 -> c_q, 2 -> c_fin
            for (;;) {
                __syncthreads();
                if (tid == 0) {
                    if (prevc) {
                        __threadfence();
                        atomicAdd(prevc == 1 ? &c_q : &c_fin, 1u);
                    }
                    s_u = (int)(atomicAdd(&g_q2, 1u) - Q2_STRIDE * (unsigned)t);
                }
                __syncthreads();
                int u = s_u;
                prevc = 0;
                if (u >= Q2_UNITS) break;
                if (u < 128) {
                    int s = u >> 3, nt = u & 7;
                    gemm_mma(g_xf + s * 64, H_,
                             Wq + (size_t)nt * 128 * H_ + s * 64, H_,
                             g_qp + (size_t)s * B_ * H_ + nt * 128, H_, 64, 0, sm);
                    prevc = 1;
                } else if (u < 192) {
                    int u2 = u - 128;
                    int s = u2 >> 3, nt = u2 & 7;
                    gemm_mma(g_xf + s * 128, H_,
                             Wm + (size_t)nt * 128 * 2 * H_ + s * 128, 2 * H_,
                             g_fp + (size_t)s * B_ * H_ + nt * 128, H_, 128, 0, sm);
                    prevc = 2;
                } else {
                    int b = (u - 192) >> 1, half = (u - 192) & 1;   // b in 0..63
                    // gate on all q tiles done
                    if (tid == 0) {
                        while ((int)(*(volatile unsigned*)&c_q - 128u * t1) < 0) { }
                    }
                    __syncthreads();
                    for (int j = tid; j < H_; j += NTHR) {
                        float a = 0.f;
#pragma unroll
                        for (int s = 0; s < SQ; s++)
                            a += __ldcg(&g_qp[((size_t)s * B_ + b) * H_ + j]);
                        sm[j] = a;
                        sm[H_ + j] = v_att[j];
                    }
                    __syncthreads();
                    int w = tid >> 5, lane = tid & 31;
                    for (int i = 0; i < 16; i++) {
                        int n = half * 256 + w * 16 + i;
                        const uint4* kp = (const uint4*)(g_keysb + (size_t)(b * N_ + n) * H_);
                        float acc = 0.f;
#pragma unroll
                        for (int j2 = 0; j2 < 4; j2++) {
                            uint4 kv = kp[lane + 32 * j2];
                            int c8 = (lane + 32 * j2) << 3;
                            float4 q0 = *(const float4*)(sm + c8);
                            float4 q1 = *(const float4*)(sm + c8 + 4);
                            float4 v0 = *(const float4*)(sm + H_ + c8);
                            float4 v1 = *(const float4*)(sm + H_ + c8 + 4);
                            acc += v0.x * tanh_fast(q0.x + __uint_as_float(kv.x << 16));
                            acc += v0.y * tanh_fast(q0.y + __uint_as_float(kv.x & 0xFFFF0000u));
                            acc += v0.z * tanh_fast(q0.z + __uint_as_float(kv.y << 16));
                            acc += v0.w * tanh_fast(q0.w + __uint_as_float(kv.y & 0xFFFF0000u));
                            acc += v1.x * tanh_fast(q1.x + __uint_as_float(kv.z << 16));
                            acc += v1.y * tanh_fast(q1.y + __uint_as_float(kv.z & 0xFFFF0000u));
                            acc += v1.z * tanh_fast(q1.z + __uint_as_float(kv.w << 16));
                            acc += v1.w * tanh_fast(q1.w + __uint_as_float(kv.w & 0xFFFF0000u));
                        }
#pragma unroll
                        for (int o = 16; o; o >>= 1) acc += __shfl_xor_sync(0xffffffffu, acc, o);
                        if (lane == 0) {
                            float mk = vmask[b * N_ + n];
                            g_score[b * N_ + n] = (mk > 0.f) ? acc : -1e9f;
                        }
                    }
                    __syncthreads();
                    if (tid == 0) {
                        __threadfence();
                        unsigned old = atomicAdd(&g_bc[b], 1u);
                        s_flag = (int)(old & 1u);
                    }
                    __syncthreads();
                    if (s_flag) {
                        __threadfence();
                        float s0 = __ldcg(&g_score[b * N_ + tid]);
                        float m = s0;
#pragma unroll
                        for (int o = 16; o; o >>= 1) m = fmaxf(m, __shfl_xor_sync(0xffffffffu, m, o));
                        if (lane == 0) red[w] = m;
                        __syncthreads();
                        float M = red[0];
#pragma unroll
                        for (int i2 = 1; i2 < 16; i2++) M = fmaxf(M, red[i2]);
                        float p = expf(s0 - M);
                        float ss = p;
#pragma unroll
                        for (int o = 16; o; o >>= 1) ss += __shfl_xor_sync(0xffffffffu, ss, o);
                        if (lane == 0) red[16 + w] = ss;
                        __syncthreads();
                        float Z = red[16];
#pragma unroll
                        for (int i2 = 1; i2 < 16; i2++) Z += red[16 + i2];
                        float a = p / Z;
                        attn_out[((size_t)b * L_ + t) * N_ + tid] = a;
                        sm[tid] = a;
                        __syncthreads();
                        // final_c[b, 2tid..2tid+1] = sum_n attn * VW[b,n,:] (coalesced)
                        const __nv_bfloat162* vp =
                            (const __nv_bfloat162*)(g_vw + (size_t)b * N_ * H_) + tid;
                        float a0 = 0.f, a1 = 0.f;
#pragma unroll 8
                        for (int n = 0; n < N_; n++) {
                            float2 f = __bfloat1622float2(vp[(size_t)n * (H_ / 2)]);
                            float wv = sm[n];
                            a0 += wv * f.x;
                            a1 += wv * f.y;
                        }
                        g_fc[b * H_ + 2 * tid]     = a0;
                        g_fc[b * H_ + 2 * tid + 1] = a1;
                        prevc = 2;   // posts c_fin on next fetch
                    }
                }
            }
        }
        waitc(&c_fin, 128u * t1);   // 64 final-rnn + 64 per-b softmax posts

        // ---- P8: final elementwise ----
        {
            int i = bid * NTHR + tid;
            if (i < B_ * H_) {
                int b = i >> 10, j = i & 1023;
                float a = bm[j] + __ldcg(&g_fc[i]);
#pragma unroll
                for (int s = 0; s < SF; s++)
                    a += __ldcg(&g_fp[((size_t)s * B_ + b) * H_ + j]);
                float y = tanhf(a);
                out[((size_t)b * L_ + t) * H_ + j] = y;
                g_h[i] = y;
            }
        }
        incc(&c_p8);
    }

    // ---- end: last CTA resets all monotone state for next graph replay ----
    __syncthreads();
    if (tid == 0) {
        __threadfence();
        unsigned old = atomicAdd(&c_end, 1u);
        if (old == NBLK - 1u) {
            g_q0 = 0; g_q1 = 0; g_q2 = 0;
            c_p1 = 0; c_p2 = 0; c_q = 0; c_fin = 0; c_p8 = 0;
            for (int b = 0; b < B_; b++) g_bc[b] = 0;
            __threadfence();
            atomicExch(&c_end, 0u);
        }
    }
}

// ---------------- launch: ONE graph node ----------------
extern "C" void kernel_launch(void* const* d_in, const int* in_sizes, int n_in,
                              void* d_out, int out_size) {
    const float* emb    = (const float*)d_in[0];
    const float* value  = (const float*)d_in[1];
    const float* vmask  = (const float*)d_in[2];
    const float* state  = (const float*)d_in[3];
    const float* W_ih   = (const float*)d_in[4];
    const float* b_ih   = (const float*)d_in[5];
    const float* W_hh   = (const float*)d_in[6];
    const float* b_hh   = (const float*)d_in[7];
    const float* Wq     = (const float*)d_in[8];
    const float* Wk     = (const float*)d_in[9];
    const float* v_att  = (const float*)d_in[10];
    const float* Wm     = (const float*)d_in[11];
    const float* bm     = (const float*)d_in[12];

    float* out      = (float*)d_out;                 // outputs: B x L x H
    float* attn_out = out + (size_t)B_ * L_ * H_;    // attns:   B x L x N

    decoder_all<<<NBLK, NTHR>>>(emb, value, vmask, state, W_ih, b_ih, W_hh, b_hh,
                                Wq, Wk, v_att, Wm, bm, out, attn_out);
}

// round 13
// speedup vs baseline: 1.5552x; 1.0860x over previous
#include <cuda_runtime.h>
#include <cuda_bf16.h>
#include <math.h>

#define B_ 64
#define L_ 128
#define E_ 512
#define N_ 512
#define H_ 1024
#define G3 3072
#define KA 1536
#define NBLK 296
#define NTHR 256
#define NGRP 37          /* 296/8 hierarchical barrier groups */

#define S1 8             /* splits for gx-h / gh (Kc=128) */
#define SQ 16            /* q splits (Kc=64) */
#define SF 8             /* final rnn splits (Kc=128) */

#define Q1_UNITS 384
#define Q2_UNITS 448     /* 128 q + 64 final-rnn + 256 score quarters */
#define Q1_STRIDE (384u + 296u)
#define Q2_STRIDE (448u + 296u)
#define P0_UNITS (8192 + 3072)

// ---------------- device scratch (static, no allocations) ----------------
__device__ __nv_bfloat16 g_keysb[(size_t)B_ * N_ * H_];  // 67 MB
__device__ __nv_bfloat16 g_vw[(size_t)B_ * N_ * H_];     // 67 MB: value @ Wm_ctx^T
__device__ float g_gxe[(size_t)B_ * L_ * G3];            // 100 MB
__device__ float g_h[B_ * H_];
__device__ float g_xf[B_ * H_];
__device__ float g_score[B_ * N_];
__device__ float g_attn[B_ * N_];
__device__ float g_gxp[(size_t)S1 * B_ * G3];
__device__ float g_ghp[(size_t)S1 * B_ * G3];
__device__ float g_qp[(size_t)SQ * B_ * H_];
__device__ float g_fp[(size_t)SF * B_ * H_];
// monotone sync state (reset by last CTA at end of each launch)
__device__ unsigned g_q0, g_q1, g_q2;
__device__ unsigned c_p1, c_q, c_fin, c_end;
__device__ unsigned c_p2, c_p8;                  // hierarchical roots (37/step)
__device__ unsigned g_grp[2 * NGRP * 16];        // group counters, 64B apart
__device__ unsigned g_bc[B_];

__device__ __forceinline__ float tanh_fast(float x) {
    float y;
    asm("tanh.approx.f32 %0, %1;" : "=f"(y) : "f"(x));
    return y;
}

__device__ __forceinline__ void waitc(unsigned* c, unsigned tgt) {
    __syncthreads();
    if (threadIdx.x == 0) {
        while ((int)(*(volatile unsigned*)c - tgt) < 0) __nanosleep(64);
    }
    __syncthreads();
}
// hierarchical arrive: 8 CTAs per group -> group-last posts root (root hits 37/step)
__device__ __forceinline__ void incc2(int phase, unsigned* root) {
    __syncthreads();
    if (threadIdx.x == 0) {
        __threadfence();
        unsigned v = atomicAdd(&g_grp[(phase * NGRP + ((int)blockIdx.x >> 3)) * 16], 1u);
        if ((v & 7u) == 7u) atomicAdd(root, 1u);
    }
    __syncthreads();
}

// ---------------- bf16 split helpers ----------------
__device__ __forceinline__ void split2(float2 v, unsigned& hi, unsigned& lo) {
    __nv_bfloat16 hx = __float2bfloat16_rn(v.x);
    __nv_bfloat16 hy = __float2bfloat16_rn(v.y);
    float rx = v.x - __bfloat162float(hx);
    float ry = v.y - __bfloat162float(hy);
    __nv_bfloat162 h2; h2.x = hx; h2.y = hy;
    __nv_bfloat162 l2 = __floats2bfloat162_rn(rx, ry);
    hi = *(unsigned*)&h2;
    lo = *(unsigned*)&l2;
}

#define MMA16816(c0,c1,c2,c3,a0,a1,a2,a3,b0,b1) \
    asm volatile("mma.sync.aligned.m16n8k16.row.col.f32.bf16.bf16.f32 " \
        "{%0,%1,%2,%3},{%4,%5,%6,%7},{%8,%9},{%0,%1,%2,%3};" \
        : "+f"(c0),"+f"(c1),"+f"(c2),"+f"(c3) \
        : "r"(a0),"r"(a1),"r"(a2),"r"(a3),"r"(b0),"r"(b1))

// ---------------- 64(M) x 128(N) x Kc GEMM tile, split-bf16 MMA, 256 threads --
// C[m][n] = sum_k Ap[m*lda+k] * Wp[n*ldw+k]   (hh + hl + lh)
// smem per parity (words): [Ah 64x12][Al 64x12][Wh 128x12][Wl 128x12] = 4608
__device__ __forceinline__ void gemm_mma(
    const float* __restrict__ Ap, int lda,
    const float* __restrict__ Wp, int ldw,
    void* Co, int ldc, int Kc, int bf16out, float* smf)
{
    unsigned* smu = (unsigned*)smf;
    const int tid = threadIdx.x;
    const int lane = tid & 31;
    const int wid = tid >> 5;                 // 0..7
    const int g = lane >> 2, tg = lane & 3;
    const int wm = (wid & 3) << 4;            // 0/16/32/48
    const int wn = (wid >> 2) << 6;           // 0/64
    const int nkt = Kc >> 4;

    float acc[8][4] = {};

    float2 apf[2], wpf0[2], wpf1[2];
#pragma unroll
    for (int r2 = 0; r2 < 2; r2++) {
        int vt = tid + (r2 << 8);
        int arow = vt >> 3, akp = vt & 7;
        apf[r2]  = __ldcg((const float2*)(Ap + (size_t)arow * lda + 2 * akp));
        wpf0[r2] = *(const float2*)(Wp + (size_t)arow * ldw + 2 * akp);
        wpf1[r2] = *(const float2*)(Wp + (size_t)(arow + 64) * ldw + 2 * akp);
    }

    __syncthreads();   // protect smem from previous use
    for (int kt = 0; kt < nkt; kt++) {
        unsigned* buf = smu + (kt & 1) * 4608;
#pragma unroll
        for (int r2 = 0; r2 < 2; r2++) {
            int vt = tid + (r2 << 8);
            int arow = vt >> 3, akp = vt & 7;
            unsigned hi, lo;
            split2(apf[r2], hi, lo);
            buf[arow * 12 + akp] = hi;
            buf[768 + arow * 12 + akp] = lo;
            split2(wpf0[r2], hi, lo);
            buf[1536 + arow * 12 + akp] = hi;
            buf[3072 + arow * 12 + akp] = lo;
            split2(wpf1[r2], hi, lo);
            buf[1536 + (arow + 64) * 12 + akp] = hi;
            buf[3072 + (arow + 64) * 12 + akp] = lo;
        }
        if (kt + 1 < nkt) {
            const float* A2 = Ap + (kt + 1) * 16;
            const float* W2 = Wp + (kt + 1) * 16;
#pragma unroll
            for (int r2 = 0; r2 < 2; r2++) {
                int vt = tid + (r2 << 8);
                int arow = vt >> 3, akp = vt & 7;
                apf[r2]  = __ldcg((const float2*)(A2 + (size_t)arow * lda + 2 * akp));
                wpf0[r2] = *(const float2*)(W2 + (size_t)arow * ldw + 2 * akp);
                wpf1[r2] = *(const float2*)(W2 + (size_t)(arow + 64) * ldw + 2 * akp);
            }
        }
        __syncthreads();
        unsigned a0h = buf[(wm + g) * 12 + tg];
        unsigned a1h = buf[(wm + g + 8) * 12 + tg];
        unsigned a2h = buf[(wm + g) * 12 + tg + 4];
        unsigned a3h = buf[(wm + g + 8) * 12 + tg + 4];
        unsigned a0l = buf[768 + (wm + g) * 12 + tg];
        unsigned a1l = buf[768 + (wm + g + 8) * 12 + tg];
        unsigned a2l = buf[768 + (wm + g) * 12 + tg + 4];
        unsigned a3l = buf[768 + (wm + g + 8) * 12 + tg + 4];
#pragma unroll
        for (int blk = 0; blk < 8; blk++) {
            int r = (wn + blk * 8 + g) * 12;
            unsigned b0h = buf[1536 + r + tg];
            unsigned b1h = buf[1536 + r + tg + 4];
            unsigned b0l = buf[3072 + r + tg];
            unsigned b1l = buf[3072 + r + tg + 4];
            MMA16816(acc[blk][0], acc[blk][1], acc[blk][2], acc[blk][3],
                     a0h, a1h, a2h, a3h, b0h, b1h);
            MMA16816(acc[blk][0], acc[blk][1], acc[blk][2], acc[blk][3],
                     a0h, a1h, a2h, a3h, b0l, b1l);
            MMA16816(acc[blk][0], acc[blk][1], acc[blk][2], acc[blk][3],
                     a0l, a1l, a2l, a3l, b0h, b1h);
        }
    }
    if (!bf16out) {
        float* C = (float*)Co;
#pragma unroll
        for (int blk = 0; blk < 8; blk++) {
            int col = wn + blk * 8 + 2 * tg;
            *(float2*)(C + (size_t)(wm + g) * ldc + col) =
                make_float2(acc[blk][0], acc[blk][1]);
            *(float2*)(C + (size_t)(wm + g + 8) * ldc + col) =
                make_float2(acc[blk][2], acc[blk][3]);
        }
    } else {
        __nv_bfloat16* C = (__nv_bfloat16*)Co;
#pragma unroll
        for (int blk = 0; blk < 8; blk++) {
            int col = wn + blk * 8 + 2 * tg;
            *(__nv_bfloat162*)(C + (size_t)(wm + g) * ldc + col) =
                __floats2bfloat162_rn(acc[blk][0], acc[blk][1]);
            *(__nv_bfloat162*)(C + (size_t)(wm + g + 8) * ldc + col) =
                __floats2bfloat162_rn(acc[blk][2], acc[blk][3]);
        }
    }
}

// ---------------- the one persistent kernel ----------------
__global__ __launch_bounds__(NTHR, 2) void decoder_all(
    const float* __restrict__ emb,   const float* __restrict__ value,
    const float* __restrict__ vmask, const float* __restrict__ state,
    const float* __restrict__ W_ih,  const float* __restrict__ b_ih,
    const float* __restrict__ W_hh,  const float* __restrict__ b_hh,
    const float* __restrict__ Wq,    const float* __restrict__ Wk,
    const float* __restrict__ v_att, const float* __restrict__ Wm,
    const float* __restrict__ bm,
    float* __restrict__ out, float* __restrict__ attn_out)
{
    __shared__ float sm[9216];   // 36 KB: 2x4608-word mma buffers; reused by score/P8
    __shared__ float red[16];
    __shared__ int   s_u;
    __shared__ int   s_flag;
    const int bid = blockIdx.x, tid = threadIdx.x;

    // ===== phase 0: init h; keys + VW + gxe GEMMs (queue 0) =====
    {
        int i = bid * NTHR + tid;
        if (i < B_ * H_) g_h[i] = state[i];
    }
    for (;;) {
        __syncthreads();
        if (tid == 0) s_u = (int)atomicAdd(&g_q0, 1u);
        __syncthreads();
        int u = s_u;
        if (u >= P0_UNITS) break;
        if (u < 8192) {
            int mt = u >> 4, sub = u & 15;
            if (sub < 8) {
                gemm_mma(value + (size_t)mt * 64 * H_, H_,
                         Wk + (size_t)sub * 128 * H_, H_,
                         g_keysb + (size_t)mt * 64 * H_ + sub * 128, H_, H_, 1, sm);
            } else {
                int nt = sub - 8;
                gemm_mma(value + (size_t)mt * 64 * H_, H_,
                         Wm + (size_t)nt * 128 * 2 * H_ + H_, 2 * H_,
                         g_vw + (size_t)mt * 64 * H_ + nt * 128, H_, H_, 1, sm);
            }
        } else {
            int u2 = u - 8192;
            int mt = u2 / 24, nt = u2 % 24;
            gemm_mma(emb + (size_t)mt * 64 * E_, E_,
                     W_ih + (size_t)nt * 128 * KA, KA,
                     g_gxe + (size_t)mt * 64 * G3 + nt * 128, G3, E_, 0, sm);
        }
    }
    incc2(1, &c_p8);   // phase-0 complete (root reaches 37)

    for (int t = 0; t < L_; t++) {
        const unsigned t1 = (unsigned)(t + 1);
        waitc(&c_p8, 37u * t1);   // h(t) ready

        // ---- Q1: gx-h (192) + gh (192), Kc=128 ----
        {
            int prev = 0;
            for (;;) {
                __syncthreads();
                if (tid == 0) {
                    if (prev) { __threadfence(); atomicAdd(&c_p1, 1u); }
                    s_u = (int)(atomicAdd(&g_q1, 1u) - Q1_STRIDE * (unsigned)t);
                }
                __syncthreads();
                int u = s_u;
                if (u >= Q1_UNITS) break;
                if (u < 192) {
                    int nt = u % 24, s = u / 24;
                    gemm_mma(g_h + s * 128, H_,
                             W_ih + (size_t)nt * 128 * KA + E_ + s * 128, KA,
                             g_gxp + (size_t)s * B_ * G3 + nt * 128, G3, 128, 0, sm);
                } else {
                    int u2 = u - 192;
                    int nt = u2 % 24, s = u2 / 24;
                    gemm_mma(g_h + s * 128, H_,
                             W_hh + (size_t)nt * 128 * H_ + s * 128, H_,
                             g_ghp + (size_t)s * B_ * G3 + nt * 128, G3, 128, 0, sm);
                }
                prev = 1;
            }
        }
        waitc(&c_p1, 384u * t1);

        // ---- P2: GRU elementwise (bids 0..255 cover B*H) ----
        {
            int i = bid * NTHR + tid;
            if (i < B_ * H_) {
                int b = i >> 10, j = i & 1023;
                const float* ge = &g_gxe[(size_t)(b * L_ + t) * G3];
                float gxr = ge[j], gxz = ge[H_ + j], gxn = ge[2 * H_ + j];
                float ghr = 0.f, ghz = 0.f, ghn = 0.f;
#pragma unroll
                for (int s = 0; s < S1; s++) {
                    const float* p = &g_gxp[((size_t)s * B_ + b) * G3];
                    gxr += __ldcg(p + j); gxz += __ldcg(p + H_ + j); gxn += __ldcg(p + 2 * H_ + j);
                }
#pragma unroll
                for (int s = 0; s < S1; s++) {
                    const float* p = &g_ghp[((size_t)s * B_ + b) * G3];
                    ghr += __ldcg(p + j); ghz += __ldcg(p + H_ + j); ghn += __ldcg(p + 2 * H_ + j);
                }
                float r = 1.f / (1.f + expf(-(gxr + b_ih[j]        + ghr + b_hh[j])));
                float z = 1.f / (1.f + expf(-(gxz + b_ih[H_ + j]   + ghz + b_hh[H_ + j])));
                float n = tanhf(gxn + b_ih[2 * H_ + j] + r * (ghn + b_hh[2 * H_ + j]));
                float h = g_h[i];
                g_xf[i] = (1.f - z) * n + z * h;
            }
        }
        incc2(0, &c_p2);
        waitc(&c_p2, 37u * t1);

        // ---- Q2: q tiles(128) | final-rnn(64) | score quarters(256) ----
        {
            int prevc = 0;   // 0 none, 1 -> c_q, 2 -> c_fin
            for (;;) {
                __syncthreads();
                if (tid == 0) {
                    if (prevc) {
                        __threadfence();
                        atomicAdd(prevc == 1 ? &c_q : &c_fin, 1u);
                    }
                    s_u = (int)(atomicAdd(&g_q2, 1u) - Q2_STRIDE * (unsigned)t);
                }
                __syncthreads();
                int u = s_u;
                prevc = 0;
                if (u >= Q2_UNITS) break;
                if (u < 128) {
                    int s = u >> 3, nt = u & 7;
                    gemm_mma(g_xf + s * 64, H_,
                             Wq + (size_t)nt * 128 * H_ + s * 64, H_,
                             g_qp + (size_t)s * B_ * H_ + nt * 128, H_, 64, 0, sm);
                    prevc = 1;
                } else if (u < 192) {
                    int u2 = u - 128;
                    int s = u2 >> 3, nt = u2 & 7;
                    gemm_mma(g_xf + s * 128, H_,
                             Wm + (size_t)nt * 128 * 2 * H_ + s * 128, 2 * H_,
                             g_fp + (size_t)s * B_ * H_ + nt * 128, H_, 128, 0, sm);
                    prevc = 2;
                } else {
                    int idx = u - 192;              // 0..255
                    int b = idx >> 2, qtr = idx & 3;
                    if (tid == 0) {
                        while ((int)(*(volatile unsigned*)&c_q - 128u * t1) < 0) __nanosleep(64);
                    }
                    __syncthreads();
                    for (int j = tid; j < H_; j += NTHR) {
                        float a = 0.f;
#pragma unroll
                        for (int s = 0; s < SQ; s++)
                            a += __ldcg(&g_qp[((size_t)s * B_ + b) * H_ + j]);
                        sm[j] = a;
                        sm[H_ + j] = v_att[j];
                    }
                    __syncthreads();
                    int w = tid >> 5, lane = tid & 31;
                    for (int i = 0; i < 16; i++) {
                        int n = qtr * 128 + w * 16 + i;
                        const uint4* kp = (const uint4*)(g_keysb + (size_t)(b * N_ + n) * H_);
                        float acc = 0.f;
#pragma unroll
                        for (int j2 = 0; j2 < 4; j2++) {
                            uint4 kv = kp[lane + 32 * j2];
                            int c8 = (lane + 32 * j2) << 3;
                            float4 q0 = *(const float4*)(sm + c8);
                            float4 q1 = *(const float4*)(sm + c8 + 4);
                            float4 v0 = *(const float4*)(sm + H_ + c8);
                            float4 v1 = *(const float4*)(sm + H_ + c8 + 4);
                            acc += v0.x * tanh_fast(q0.x + __uint_as_float(kv.x << 16));
                            acc += v0.y * tanh_fast(q0.y + __uint_as_float(kv.x & 0xFFFF0000u));
                            acc += v0.z * tanh_fast(q0.z + __uint_as_float(kv.y << 16));
                            acc += v0.w * tanh_fast(q0.w + __uint_as_float(kv.y & 0xFFFF0000u));
                            acc += v1.x * tanh_fast(q1.x + __uint_as_float(kv.z << 16));
                            acc += v1.y * tanh_fast(q1.y + __uint_as_float(kv.z & 0xFFFF0000u));
                            acc += v1.z * tanh_fast(q1.z + __uint_as_float(kv.w << 16));
                            acc += v1.w * tanh_fast(q1.w + __uint_as_float(kv.w & 0xFFFF0000u));
                        }
#pragma unroll
                        for (int o = 16; o; o >>= 1) acc += __shfl_xor_sync(0xffffffffu, acc, o);
                        if (lane == 0) {
                            float mk = vmask[b * N_ + n];
                            g_score[b * N_ + n] = (mk > 0.f) ? acc : -1e9f;
                        }
                    }
                    __syncthreads();
                    if (tid == 0) {
                        __threadfence();
                        unsigned old = atomicAdd(&g_bc[b], 1u);
                        s_flag = ((old & 3u) == 3u) ? 1 : 0;
                    }
                    __syncthreads();
                    if (s_flag) {
                        __threadfence();
                        float s0 = __ldcg(&g_score[b * N_ + tid]);
                        float s1 = __ldcg(&g_score[b * N_ + 256 + tid]);
                        float m = fmaxf(s0, s1);
#pragma unroll
                        for (int o = 16; o; o >>= 1) m = fmaxf(m, __shfl_xor_sync(0xffffffffu, m, o));
                        if (lane == 0) red[w] = m;
                        __syncthreads();
                        float M = red[0];
#pragma unroll
                        for (int i2 = 1; i2 < 8; i2++) M = fmaxf(M, red[i2]);
                        float p0 = expf(s0 - M), p1 = expf(s1 - M);
                        float ss = p0 + p1;
#pragma unroll
                        for (int o = 16; o; o >>= 1) ss += __shfl_xor_sync(0xffffffffu, ss, o);
                        if (lane == 0) red[8 + w] = ss;
                        __syncthreads();
                        float Z = red[8];
#pragma unroll
                        for (int i2 = 1; i2 < 8; i2++) Z += red[8 + i2];
                        float inv = 1.f / Z;
                        float a0 = p0 * inv, a1 = p1 * inv;
                        g_attn[b * N_ + tid] = a0;
                        g_attn[b * N_ + 256 + tid] = a1;
                        attn_out[((size_t)b * L_ + t) * N_ + tid] = a0;
                        attn_out[((size_t)b * L_ + t) * N_ + 256 + tid] = a1;
                        prevc = 2;   // posts c_fin on next fetch
                    }
                }
            }
        }
        waitc(&c_fin, 128u * t1);   // 64 final-rnn + 64 softmax posts

        // ---- P8: fused ctx-from-VW + final sum + tanh; 128 (b, half-H) units ----
        if (bid < 128) {
            int b = bid >> 1, half = bid & 1;
            sm[tid] = __ldcg(&g_attn[b * N_ + tid]);
            sm[256 + tid] = __ldcg(&g_attn[b * N_ + 256 + tid]);
            __syncthreads();
            int pair = half * 256 + tid;                   // bf162 pair index
            const __nv_bfloat162* vp =
                (const __nv_bfloat162*)(g_vw + (size_t)b * N_ * H_) + pair;
            float a0 = 0.f, a1 = 0.f;
#pragma unroll 8
            for (int n = 0; n < N_; n++) {
                float2 f = __bfloat1622float2(vp[(size_t)n * (H_ / 2)]);
                float wv = sm[n];
                a0 += wv * f.x;
                a1 += wv * f.y;
            }
            int h0 = 2 * pair;
            float v0 = bm[h0] + a0;
            float v1 = bm[h0 + 1] + a1;
#pragma unroll
            for (int s = 0; s < SF; s++) {
                float2 fp2 = __ldcg((const float2*)&g_fp[((size_t)s * B_ + b) * H_ + h0]);
                v0 += fp2.x;
                v1 += fp2.y;
            }
            float y0 = tanhf(v0), y1 = tanhf(v1);
            *(float2*)&out[((size_t)b * L_ + t) * H_ + h0] = make_float2(y0, y1);
            *(float2*)&g_h[b * H_ + h0] = make_float2(y0, y1);
        }
        incc2(1, &c_p8);
    }

    // ---- end: last CTA resets all monotone state for next graph replay ----
    __syncthreads();
    if (tid == 0) {
        __threadfence();
        unsigned old = atomicAdd(&c_end, 1u);
        if (old == NBLK - 1u) {
            g_q0 = 0; g_q1 = 0; g_q2 = 0;
            c_p1 = 0; c_p2 = 0; c_q = 0; c_fin = 0; c_p8 = 0;
            for (int i = 0; i < 2 * NGRP * 16; i++) g_grp[i] = 0;
            for (int b = 0; b < B_; b++) g_bc[b] = 0;
            __threadfence();
            atomicExch(&c_end, 0u);
        }
    }
}

// ---------------- launch: ONE graph node ----------------
extern "C" void kernel_launch(void* const* d_in, const int* in_sizes, int n_in,
                              void* d_out, int out_size) {
    const float* emb    = (const float*)d_in[0];
    const float* value  = (const float*)d_in[1];
    const float* vmask  = (const float*)d_in[2];
    const float* state  = (const float*)d_in[3];
    const float* W_ih   = (const float*)d_in[4];
    const float* b_ih   = (const float*)d_in[5];
    const float* W_hh   = (const float*)d_in[6];
    const float* b_hh   = (const float*)d_in[7];
    const float* Wq     = (const float*)d_in[8];
    const float* Wk     = (const float*)d_in[9];
    const float* v_att  = (const float*)d_in[10];
    const float* Wm     = (const float*)d_in[11];
    const float* bm     = (const float*)d_in[12];

    float* out      = (float*)d_out;                 // outputs: B x L x H
    float* attn_out = out + (size_t)B_ * L_ * H_;    // attns:   B x L x N

    decoder_all<<<NBLK, NTHR>>>(emb, value, vmask, state, W_ih, b_ih, W_hh, b_hh,
                                Wq, Wk, v_att, Wm, bm, out, attn_out);
}